// round 7
// baseline (speedup 1.0000x reference)
#include <cuda_runtime.h>
#include <cuda_bf16.h>
#include <cstdint>

// phi = exp(-sum_d |x[i,d]-g[j,d]|/ls[d]) @ chol_inv (lower-tri), [4096,4096] fp32.
// Engine: mma.sync bf16 (HMMA) hi/lo split x3, triangular K-start.
// R6: CTA tile 256x128, BK=64, 8 warps, 2-stage, 1 CTA/SM (fewer cp.async/MAC, fewer syncs).

#define N_PTS 4096
#define M_PTS 4096
#define DIMS 8

__device__ __nv_bfloat16 g_Ah[(size_t)N_PTS * M_PTS];
__device__ __nv_bfloat16 g_Al[(size_t)N_PTS * M_PTS];
__device__ __nv_bfloat16 g_Bh[(size_t)M_PTS * M_PTS];  // B^T: [j, k]
__device__ __nv_bfloat16 g_Bl[(size_t)M_PTS * M_PTS];

__device__ __forceinline__ uint32_t smem_u32(const void* p) {
    uint32_t a;
    asm("{ .reg .u64 t; cvta.to.shared.u64 t, %1; cvt.u32.u64 %0, t; }" : "=r"(a) : "l"(p));
    return a;
}

// ---------------------------------------------------------------------------
// Stage 1: k_star rows -> bf16 hi/lo (exp2 path)
// ---------------------------------------------------------------------------
__global__ __launch_bounds__(256) void kstar_split(
    const float* __restrict__ x, const float* __restrict__ grid,
    const float* __restrict__ ls)
{
    const int i = blockIdx.x;
    __shared__ float xs[DIMS], rls[DIMS];
    if (threadIdx.x < DIMS) {
        xs[threadIdx.x]  = x[(size_t)i * DIMS + threadIdx.x];
        rls[threadIdx.x] = 1.442695040888963f / ls[threadIdx.x];
    }
    __syncthreads();
    float xr[DIMS], rl[DIMS];
#pragma unroll
    for (int d = 0; d < DIMS; d++) { xr[d] = xs[d]; rl[d] = rls[d]; }

    const float4* g4 = reinterpret_cast<const float4*>(grid);
    __nv_bfloat16* oh = g_Ah + (size_t)i * M_PTS;
    __nv_bfloat16* ol = g_Al + (size_t)i * M_PTS;

    for (int j = threadIdx.x; j < M_PTS; j += blockDim.x) {
        float4 a = g4[2 * j];
        float4 b = g4[2 * j + 1];
        float s = fabsf(xr[0] - a.x) * rl[0] + fabsf(xr[1] - a.y) * rl[1]
                + fabsf(xr[2] - a.z) * rl[2] + fabsf(xr[3] - a.w) * rl[3]
                + fabsf(xr[4] - b.x) * rl[4] + fabsf(xr[5] - b.y) * rl[5]
                + fabsf(xr[6] - b.z) * rl[6] + fabsf(xr[7] - b.w) * rl[7];
        float e = exp2f(-s);
        __nv_bfloat16 h = __float2bfloat16(e);
        float rem = e - __bfloat162float(h);
        oh[j] = h;
        ol[j] = __float2bfloat16(rem);
    }
}

// ---------------------------------------------------------------------------
// Stage 2: transpose chol -> B^T[j,k] bf16 hi/lo
// ---------------------------------------------------------------------------
__global__ __launch_bounds__(256) void transpose_split(const float* __restrict__ chol)
{
    __shared__ float t[32][33];
    const int tx = threadIdx.x, ty = threadIdx.y;   // (32, 8)
    const int j0 = blockIdx.x * 32, k0 = blockIdx.y * 32;
#pragma unroll
    for (int r = 0; r < 32; r += 8)
        t[ty + r][tx] = chol[(size_t)(k0 + ty + r) * M_PTS + j0 + tx];
    __syncthreads();
#pragma unroll
    for (int r = 0; r < 32; r += 8) {
        float v = t[tx][ty + r];
        __nv_bfloat16 h = __float2bfloat16(v);
        float rem = v - __bfloat162float(h);
        size_t o = (size_t)(j0 + ty + r) * M_PTS + k0 + tx;
        g_Bh[o] = h;
        g_Bl[o] = __float2bfloat16(rem);
    }
}

// ---------------------------------------------------------------------------
// Stage 3: HMMA GEMM. CTA 256x128, BK=64, 8 warps (64x64 each), 2-stage.
// Padded smem stride 72 elems (144B): rows cycle 16B phases mod 128 ->
// conflict-free ldmatrix.
// ---------------------------------------------------------------------------
#define BK 64
#define KSTRIDE 72
#define A_TILE_B (256 * KSTRIDE * 2)            // 36864
#define B_TILE_B (128 * KSTRIDE * 2)            // 18432
#define STAGE_B (2 * A_TILE_B + 2 * B_TILE_B)   // 110592
#define SMEM_B (2 * STAGE_B)                    // 221184

__device__ __forceinline__ void ldm4(uint32_t* r, uint32_t addr) {
    asm volatile("ldmatrix.sync.aligned.m8n8.x4.shared.b16 {%0,%1,%2,%3}, [%4];"
                 : "=r"(r[0]), "=r"(r[1]), "=r"(r[2]), "=r"(r[3]) : "r"(addr));
}
__device__ __forceinline__ void mma_bf16(float* c, const uint32_t* a, const uint32_t* b) {
    asm volatile(
        "mma.sync.aligned.m16n8k16.row.col.f32.bf16.bf16.f32 "
        "{%0,%1,%2,%3}, {%4,%5,%6,%7}, {%8,%9}, {%0,%1,%2,%3};"
        : "+f"(c[0]), "+f"(c[1]), "+f"(c[2]), "+f"(c[3])
        : "r"(a[0]), "r"(a[1]), "r"(a[2]), "r"(a[3]), "r"(b[0]), "r"(b[1]));
}
__device__ __forceinline__ void cpasync16(uint32_t saddr, const void* gaddr) {
    asm volatile("cp.async.cg.shared.global [%0], [%1], 16;" :: "r"(saddr), "l"(gaddr));
}

// rows16: number of 16B segments total = nrows*8; 256 threads
__device__ __forceinline__ void load_tile_rows(uint32_t sbuf, const __nv_bfloat16* src,
                                               int k, int tid, int npass)
{
#pragma unroll
    for (int p = 0; p < 8; ++p) {
        if (p >= npass) break;
        int idx = p * 256 + tid;
        int row = idx >> 3;
        int seg = idx & 7;
        cpasync16(sbuf + row * (KSTRIDE * 2) + seg * 16,
                  src + (size_t)row * M_PTS + k + seg * 8);
    }
}

__device__ __forceinline__ void issue_chunk(uint32_t buf, int row0, int col0, int k,
                                            int tid)
{
    load_tile_rows(buf,                         g_Ah + (size_t)row0 * M_PTS, k, tid, 8);
    load_tile_rows(buf + A_TILE_B,              g_Al + (size_t)row0 * M_PTS, k, tid, 8);
    load_tile_rows(buf + 2 * A_TILE_B,          g_Bh + (size_t)col0 * M_PTS, k, tid, 4);
    load_tile_rows(buf + 2 * A_TILE_B + B_TILE_B, g_Bl + (size_t)col0 * M_PTS, k, tid, 4);
}

__global__ __launch_bounds__(256, 1) void gemm_hmma(float* __restrict__ C)
{
    extern __shared__ char smem[];
    const uint32_t sb = smem_u32(smem);
    const int tid = threadIdx.x;
    const int lane = tid & 31, wid = tid >> 5;
    const int wm = wid >> 1;                  // 0..3 (64-row slabs of 256)
    const int wn = wid & 1;                   // 0..1 (64-col slabs of 128)

    const int row0 = blockIdx.y * 256;
    const int col0 = blockIdx.x * 128;
    const int k0 = col0;                      // triangular skip
    const int nchunk = (M_PTS - k0) / BK;     // >= 2

    float acc[4][8][4];
#pragma unroll
    for (int i = 0; i < 4; ++i)
#pragma unroll
        for (int j = 0; j < 8; ++j)
#pragma unroll
            for (int q = 0; q < 4; ++q) acc[i][j][q] = 0.0f;

    const int lr = lane & 7, lsel = lane >> 3;
    const int a_row_base = wm * 64 + lr + (lsel & 1) * 8;
    const int a_col_base = (lsel >> 1) * 8;
    const int b_row_base = wn * 64 + (lsel >> 1) * 8 + lr;
    const int b_col_base = (lsel & 1) * 8;

    issue_chunk(sb, row0, col0, k0, tid);
    asm volatile("cp.async.commit_group;");
    issue_chunk(sb + STAGE_B, row0, col0, k0 + BK, tid);
    asm volatile("cp.async.commit_group;");

    for (int c = 0; c < nchunk; ++c) {
        asm volatile("cp.async.wait_group 1;");
        __syncthreads();
        const uint32_t buf = sb + (c & 1) * STAGE_B;
        const uint32_t Ah = buf, Al = buf + A_TILE_B;
        const uint32_t Bh = buf + 2 * A_TILE_B, Bl = Bh + B_TILE_B;

#pragma unroll
        for (int ks = 0; ks < 4; ++ks) {
            const int kel = ks * 16;
            uint32_t ah[4][4], al[4][4], bh[4][4], bl[4][4];
#pragma unroll
            for (int i = 0; i < 4; ++i) {
                uint32_t off = (a_row_base + i * 16) * (KSTRIDE * 2)
                             + (kel + a_col_base) * 2;
                ldm4(ah[i], Ah + off);
                ldm4(al[i], Al + off);
            }
#pragma unroll
            for (int jp = 0; jp < 4; ++jp) {
                uint32_t off = (b_row_base + jp * 16) * (KSTRIDE * 2)
                             + (kel + b_col_base) * 2;
                ldm4(bh[jp], Bh + off);
                ldm4(bl[jp], Bl + off);
            }
#pragma unroll
            for (int i = 0; i < 4; ++i)
#pragma unroll
                for (int j = 0; j < 8; ++j) {
                    const uint32_t* bhj = &bh[j >> 1][(j & 1) * 2];
                    const uint32_t* blj = &bl[j >> 1][(j & 1) * 2];
                    mma_bf16(acc[i][j], ah[i], bhj);
                    mma_bf16(acc[i][j], ah[i], blj);
                    mma_bf16(acc[i][j], al[i], bhj);
                }
        }
        __syncthreads();
        if (c + 2 < nchunk)
            issue_chunk(buf, row0, col0, k0 + (c + 2) * BK, tid);
        asm volatile("cp.async.commit_group;");
    }

    // Epilogue
    const int er = lane >> 2;
    const int ec = (lane & 3) * 2;
#pragma unroll
    for (int i = 0; i < 4; ++i) {
#pragma unroll
        for (int j = 0; j < 8; ++j) {
            int r = row0 + wm * 64 + i * 16 + er;
            int cc = col0 + wn * 64 + j * 8 + ec;
            *reinterpret_cast<float2*>(C + (size_t)r * M_PTS + cc)
                = make_float2(acc[i][j][0], acc[i][j][1]);
            *reinterpret_cast<float2*>(C + (size_t)(r + 8) * M_PTS + cc)
                = make_float2(acc[i][j][2], acc[i][j][3]);
        }
    }
}

// ---------------------------------------------------------------------------
extern "C" void kernel_launch(void* const* d_in, const int* in_sizes, int n_in,
                              void* d_out, int out_size)
{
    const float* x    = (const float*)d_in[0];
    const float* grid = (const float*)d_in[1];
    const float* chol = (const float*)d_in[2];
    const float* ls   = (const float*)d_in[3];
    float* out = (float*)d_out;

    cudaFuncSetAttribute(gemm_hmma, cudaFuncAttributeMaxDynamicSharedMemorySize, SMEM_B);

    kstar_split<<<N_PTS, 256>>>(x, grid, ls);
    transpose_split<<<dim3(M_PTS / 32, M_PTS / 32), dim3(32, 8)>>>(chol);
    gemm_hmma<<<dim3(M_PTS / 128, N_PTS / 256), 256, SMEM_B>>>(out);
}

// round 9
// speedup vs baseline: 1.2581x; 1.2581x over previous
#include <cuda_runtime.h>
#include <cuda_bf16.h>
#include <cstdint>

// phi = exp(-sum_d |x[i,d]-g[j,d]|/ls[d]) @ chol_inv (lower-tri), [4096,4096] fp32.
// Engine: mma.sync bf16 (HMMA) hi/lo split x3, triangular K-start.
// R8: R5 tile shape (128x128, BK=32, 4 warps, 2 CTA/SM) + persistent CTAs with
// atomic ticket, heaviest-first, to kill triangular load imbalance.

#define N_PTS 4096
#define M_PTS 4096
#define DIMS 8
#define NTILES 1024                            // 32x32 tiles of 128x128
#define NWORKERS 296                           // 2 per SM

__device__ __nv_bfloat16 g_Ah[(size_t)N_PTS * M_PTS];
__device__ __nv_bfloat16 g_Al[(size_t)N_PTS * M_PTS];
__device__ __nv_bfloat16 g_Bh[(size_t)M_PTS * M_PTS];  // B^T: [j, k]
__device__ __nv_bfloat16 g_Bl[(size_t)M_PTS * M_PTS];
__device__ unsigned int g_ticket;

__device__ __forceinline__ uint32_t smem_u32(const void* p) {
    uint32_t a;
    asm("{ .reg .u64 t; cvta.to.shared.u64 t, %1; cvt.u32.u64 %0, t; }" : "=r"(a) : "l"(p));
    return a;
}

__global__ void reset_ticket() { g_ticket = 0; }

// ---------------------------------------------------------------------------
// Stage 1: k_star rows -> bf16 hi/lo (exp2 path)
// ---------------------------------------------------------------------------
__global__ __launch_bounds__(256) void kstar_split(
    const float* __restrict__ x, const float* __restrict__ grid,
    const float* __restrict__ ls)
{
    const int i = blockIdx.x;
    __shared__ float xs[DIMS], rls[DIMS];
    if (threadIdx.x < DIMS) {
        xs[threadIdx.x]  = x[(size_t)i * DIMS + threadIdx.x];
        rls[threadIdx.x] = 1.442695040888963f / ls[threadIdx.x];
    }
    __syncthreads();
    float xr[DIMS], rl[DIMS];
#pragma unroll
    for (int d = 0; d < DIMS; d++) { xr[d] = xs[d]; rl[d] = rls[d]; }

    const float4* g4 = reinterpret_cast<const float4*>(grid);
    __nv_bfloat16* oh = g_Ah + (size_t)i * M_PTS;
    __nv_bfloat16* ol = g_Al + (size_t)i * M_PTS;

    for (int j = threadIdx.x; j < M_PTS; j += blockDim.x) {
        float4 a = g4[2 * j];
        float4 b = g4[2 * j + 1];
        float s = fabsf(xr[0] - a.x) * rl[0] + fabsf(xr[1] - a.y) * rl[1]
                + fabsf(xr[2] - a.z) * rl[2] + fabsf(xr[3] - a.w) * rl[3]
                + fabsf(xr[4] - b.x) * rl[4] + fabsf(xr[5] - b.y) * rl[5]
                + fabsf(xr[6] - b.z) * rl[6] + fabsf(xr[7] - b.w) * rl[7];
        float e = exp2f(-s);
        __nv_bfloat16 h = __float2bfloat16(e);
        float rem = e - __bfloat162float(h);
        oh[j] = h;
        ol[j] = __float2bfloat16(rem);
    }
}

// ---------------------------------------------------------------------------
// Stage 2: transpose chol -> B^T[j,k] bf16 hi/lo
// ---------------------------------------------------------------------------
__global__ __launch_bounds__(256) void transpose_split(const float* __restrict__ chol)
{
    __shared__ float t[32][33];
    const int tx = threadIdx.x, ty = threadIdx.y;   // (32, 8)
    const int j0 = blockIdx.x * 32, k0 = blockIdx.y * 32;
#pragma unroll
    for (int r = 0; r < 32; r += 8)
        t[ty + r][tx] = chol[(size_t)(k0 + ty + r) * M_PTS + j0 + tx];
    __syncthreads();
#pragma unroll
    for (int r = 0; r < 32; r += 8) {
        float v = t[tx][ty + r];
        __nv_bfloat16 h = __float2bfloat16(v);
        float rem = v - __bfloat162float(h);
        size_t o = (size_t)(j0 + ty + r) * M_PTS + k0 + tx;
        g_Bh[o] = h;
        g_Bl[o] = __float2bfloat16(rem);
    }
}

// ---------------------------------------------------------------------------
// Stage 3: persistent HMMA GEMM. Tile 128x128, BK=32, 4 warps (64x64 each),
// cp.async double-buffer, padded stride 40 elems, 2 CTAs/SM.
// ---------------------------------------------------------------------------
#define BK 32
#define KSTRIDE 40
#define TILE_B (128 * KSTRIDE * 2)              // 10240 bytes
#define BUF_B (4 * TILE_B)                      // 40960
#define SMEM_B (2 * BUF_B)                      // 81920

__device__ __forceinline__ void ldm4(uint32_t* r, uint32_t addr) {
    asm volatile("ldmatrix.sync.aligned.m8n8.x4.shared.b16 {%0,%1,%2,%3}, [%4];"
                 : "=r"(r[0]), "=r"(r[1]), "=r"(r[2]), "=r"(r[3]) : "r"(addr));
}
__device__ __forceinline__ void mma_bf16(float* c, const uint32_t* a, const uint32_t* b) {
    asm volatile(
        "mma.sync.aligned.m16n8k16.row.col.f32.bf16.bf16.f32 "
        "{%0,%1,%2,%3}, {%4,%5,%6,%7}, {%8,%9}, {%0,%1,%2,%3};"
        : "+f"(c[0]), "+f"(c[1]), "+f"(c[2]), "+f"(c[3])
        : "r"(a[0]), "r"(a[1]), "r"(a[2]), "r"(a[3]), "r"(b[0]), "r"(b[1]));
}
__device__ __forceinline__ void cpasync16(uint32_t saddr, const void* gaddr) {
    asm volatile("cp.async.cg.shared.global [%0], [%1], 16;" :: "r"(saddr), "l"(gaddr));
}

__device__ __forceinline__ void issue_chunk(uint32_t buf, int row0, int col0, int k,
                                            int tid)
{
    const __nv_bfloat16* srcs[4] = {
        g_Ah + (size_t)row0 * M_PTS, g_Al + (size_t)row0 * M_PTS,
        g_Bh + (size_t)col0 * M_PTS, g_Bl + (size_t)col0 * M_PTS };
#pragma unroll
    for (int t = 0; t < 4; ++t) {
        uint32_t sb = buf + t * TILE_B;
        const __nv_bfloat16* src = srcs[t];
#pragma unroll
        for (int p = 0; p < 4; ++p) {          // 512 x 16B per tile / 128 thr
            int idx = p * 128 + tid;
            int row = idx >> 2;
            int seg = idx & 3;
            cpasync16(sb + row * (KSTRIDE * 2) + seg * 16,
                      src + (size_t)row * M_PTS + k + seg * 8);
        }
    }
}

__global__ __launch_bounds__(128, 2) void gemm_hmma(float* __restrict__ C)
{
    extern __shared__ char smem[];
    const uint32_t sb = smem_u32(smem);
    const int tid = threadIdx.x;
    const int lane = tid & 31, wid = tid >> 5;
    const int wm = wid >> 1;                  // 0..1 (64-row slabs)
    const int wn = wid & 1;                   // 0..1 (64-col slabs)

    const int lr = lane & 7, lsel = lane >> 3;
    const int a_row_base0 = wm * 64 + lr + (lsel & 1) * 8;
    const int a_col_base = (lsel >> 1) * 8;
    const int b_row_base0 = wn * 64 + (lsel >> 1) * 8 + lr;
    const int b_col_base = (lsel & 1) * 8;

    __shared__ unsigned int s_tile;

    for (;;) {
        if (tid == 0) s_tile = atomicAdd(&g_ticket, 1u);
        __syncthreads();
        const unsigned int t = s_tile;
        __syncthreads();
        if (t >= NTILES) break;

        // cb ascending == heaviest first (k0 = col0 triangular skip)
        const int cb = (int)(t >> 5), rb = (int)(t & 31);
        const int row0 = rb * 128;
        const int col0 = cb * 128;
        const int k0 = col0;
        const int nchunk = (M_PTS - k0) / BK;

        float acc[4][8][4];
#pragma unroll
        for (int i = 0; i < 4; ++i)
#pragma unroll
            for (int j = 0; j < 8; ++j)
#pragma unroll
                for (int q = 0; q < 4; ++q) acc[i][j][q] = 0.0f;

        issue_chunk(sb, row0, col0, k0, tid);
        asm volatile("cp.async.commit_group;");
        if (nchunk > 1) issue_chunk(sb + BUF_B, row0, col0, k0 + BK, tid);
        asm volatile("cp.async.commit_group;");

        for (int c = 0; c < nchunk; ++c) {
            asm volatile("cp.async.wait_group 1;");
            __syncthreads();
            const uint32_t buf = sb + (c & 1) * BUF_B;
            const uint32_t Ah = buf, Al = buf + TILE_B;
            const uint32_t Bh = buf + 2 * TILE_B, Bl = buf + 3 * TILE_B;

#pragma unroll
            for (int ks = 0; ks < 2; ++ks) {
                const int kel = ks * 16;
                uint32_t ah[4][4], al[4][4], bh[4][4], bl[4][4];
#pragma unroll
                for (int i = 0; i < 4; ++i) {
                    uint32_t off = (a_row_base0 + i * 16) * (KSTRIDE * 2)
                                 + (kel + a_col_base) * 2;
                    ldm4(ah[i], Ah + off);
                    ldm4(al[i], Al + off);
                }
#pragma unroll
                for (int jp = 0; jp < 4; ++jp) {
                    uint32_t off = (b_row_base0 + jp * 16) * (KSTRIDE * 2)
                                 + (kel + b_col_base) * 2;
                    ldm4(bh[jp], Bh + off);
                    ldm4(bl[jp], Bl + off);
                }
#pragma unroll
                for (int i = 0; i < 4; ++i)
#pragma unroll
                    for (int j = 0; j < 8; ++j) {
                        const uint32_t* bhj = &bh[j >> 1][(j & 1) * 2];
                        const uint32_t* blj = &bl[j >> 1][(j & 1) * 2];
                        mma_bf16(acc[i][j], ah[i], bhj);
                        mma_bf16(acc[i][j], ah[i], blj);
                        mma_bf16(acc[i][j], al[i], bhj);
                    }
            }
            __syncthreads();
            if (c + 2 < nchunk)
                issue_chunk(buf, row0, col0, k0 + (c + 2) * BK, tid);
            asm volatile("cp.async.commit_group;");
        }

        // Drain pipeline before smem reuse by the next tile
        asm volatile("cp.async.wait_group 0;");
        __syncthreads();

        // Epilogue
        const int er = lane >> 2;
        const int ec = (lane & 3) * 2;
#pragma unroll
        for (int i = 0; i < 4; ++i) {
#pragma unroll
            for (int j = 0; j < 8; ++j) {
                int r = row0 + wm * 64 + i * 16 + er;
                int cc = col0 + wn * 64 + j * 8 + ec;
                *reinterpret_cast<float2*>(C + (size_t)r * M_PTS + cc)
                    = make_float2(acc[i][j][0], acc[i][j][1]);
                *reinterpret_cast<float2*>(C + (size_t)(r + 8) * M_PTS + cc)
                    = make_float2(acc[i][j][2], acc[i][j][3]);
            }
        }
    }
}

// ---------------------------------------------------------------------------
extern "C" void kernel_launch(void* const* d_in, const int* in_sizes, int n_in,
                              void* d_out, int out_size)
{
    const float* x    = (const float*)d_in[0];
    const float* grid = (const float*)d_in[1];
    const float* chol = (const float*)d_in[2];
    const float* ls   = (const float*)d_in[3];
    float* out = (float*)d_out;

    cudaFuncSetAttribute(gemm_hmma, cudaFuncAttributeMaxDynamicSharedMemorySize, SMEM_B);

    reset_ticket<<<1, 1>>>();
    kstar_split<<<N_PTS, 256>>>(x, grid, ls);
    transpose_split<<<dim3(M_PTS / 32, M_PTS / 32), dim3(32, 8)>>>(chol);
    gemm_hmma<<<NWORKERS, 128, SMEM_B>>>(out);
}